// round 5
// baseline (speedup 1.0000x reference)
#include <cuda_runtime.h>

#define R  2000
#define D  128
#define H  4
#define NMAX 500000

// ---------------- device scratch (no allocations allowed) ----------------
__device__ __align__(16) float g_qvec[D];      // seed query, flattened [128]
__device__ __align__(16) float g_A[D * H];     // A[d][h] = (Wk^T q_h)[d] / sqrt(D)
__device__ __align__(16) float g_c[4];         // bias term of scores per head
__device__ __align__(16) float g_e[NMAX * 4];  // per-POI softmax numerators (4 heads)
__device__ int   g_hist[R];
__device__ int   g_off[R + 1];
__device__ int   g_cursor[R];
__device__ int   g_perm[NMAX];
__device__ float g_deg[R];
__device__ __align__(16) float g_O[R * D];     // PMA output (pre-rFF)
__device__ __align__(16) float g_hfeat[R * D]; // O2 @ Wg^T
__device__ __align__(16) float g_accG[R * D];  // GCN scatter accumulator
__device__ __align__(16) float g_WoT[D * D];
__device__ __align__(16) float g_WgT[D * D];

// ---------------- init: zero accumulators / counters ----------------
__global__ void k_init() {
    int i = blockIdx.x * blockDim.x + threadIdx.x;
    if (i < R * D) g_accG[i] = 0.f;
    if (i < R) { g_deg[i] = 1.0f; g_hist[i] = 0; g_cursor[i] = 0; }
}

// ---------------- prep: q = Wq S + bq ; A = (Wk^T q)/sqrt(D) ; transposes ----------------
__global__ void k_prep(const float* __restrict__ S,  const float* __restrict__ Wq,
                       const float* __restrict__ bq, const float* __restrict__ Wk,
                       const float* __restrict__ bk, const float* __restrict__ Wo,
                       const float* __restrict__ Wg) {
    __shared__ float s_S[D];
    __shared__ float s_q[D];
    int t = threadIdx.x;  // 128 threads
    s_S[t] = S[t];
    __syncthreads();
    float acc = bq[t];
    for (int d = 0; d < D; d++) acc = fmaf(s_S[d], Wq[t * D + d], acc);
    s_q[t] = acc;
    g_qvec[t] = acc;
    __syncthreads();
    const float scale = 0.08838834764831845f;  // 1/sqrt(128)
    int d = t;
    float a0 = 0.f, a1 = 0.f, a2 = 0.f, a3 = 0.f;
    for (int e = 0; e < 32; e++) {
        a0 = fmaf(s_q[0 * 32 + e], Wk[(0 * 32 + e) * D + d], a0);
        a1 = fmaf(s_q[1 * 32 + e], Wk[(1 * 32 + e) * D + d], a1);
        a2 = fmaf(s_q[2 * 32 + e], Wk[(2 * 32 + e) * D + d], a2);
        a3 = fmaf(s_q[3 * 32 + e], Wk[(3 * 32 + e) * D + d], a3);
    }
    g_A[d * H + 0] = a0 * scale;
    g_A[d * H + 1] = a1 * scale;
    g_A[d * H + 2] = a2 * scale;
    g_A[d * H + 3] = a3 * scale;
    if (t < H) {
        float cc = 0.f;
        for (int e = 0; e < 32; e++) cc = fmaf(s_q[t * 32 + e], bk[t * 32 + e], cc);
        g_c[t] = cc * scale;
    }
    // transpose Wo, Wg for coalesced column access in k_ff
    for (int i = t; i < D * D; i += blockDim.x) {
        int j = i >> 7, dd = i & 127;
        g_WoT[dd * D + j] = Wo[i];
        g_WgT[dd * D + j] = Wg[i];
    }
}

// ---------------- zone histogram + in-degree (fused) ----------------
__global__ void k_hist_deg(const int* __restrict__ zone, const int* __restrict__ adj,
                           int N, int E) {
    int i = blockIdx.x * blockDim.x + threadIdx.x;
    if (i < N) {
        atomicAdd(&g_hist[zone[i]], 1);
    } else if (i < N + E) {
        int e = i - N;
        atomicAdd(&g_deg[adj[E + e]], 1.0f);
    }
}

// ---------------- exclusive scan over hist (warp-scan, 1024 threads) ----------------
__global__ void k_scan() {
    int t = threadIdx.x, lane = t & 31, w = t >> 5;
    int i0 = 2 * t, i1 = 2 * t + 1;
    int v0 = (i0 < R) ? g_hist[i0] : 0;
    int v1 = (i1 < R) ? g_hist[i1] : 0;
    int s = v0 + v1;
    int incl = s;
    #pragma unroll
    for (int o = 1; o < 32; o <<= 1) {
        int n = __shfl_up_sync(0xffffffffu, incl, o);
        if (lane >= o) incl += n;
    }
    __shared__ int wsum[32];
    if (lane == 31) wsum[w] = incl;
    __syncthreads();
    if (w == 0) {
        int wi = wsum[lane];
        #pragma unroll
        for (int o = 1; o < 32; o <<= 1) {
            int n = __shfl_up_sync(0xffffffffu, wi, o);
            if (lane >= o) wi += n;
        }
        wsum[lane] = wi;
    }
    __syncthreads();
    int excl = incl - s + (w ? wsum[w - 1] : 0);
    if (i0 <= R) g_off[i0] = excl;
    if (i1 <= R) g_off[i1] = excl + v0;
}

// ---------------- scatter permutation (counting sort by zone) ----------------
__global__ void k_scatter(const int* __restrict__ zone, int N) {
    int i = blockIdx.x * blockDim.x + threadIdx.x;
    if (i < N) {
        int z = zone[i];
        int p = atomicAdd(&g_cursor[z], 1);
        g_perm[g_off[z] + p] = i;
    }
}

// ---------------- pass A: streaming score/exp over x in natural order ----------------
// Block stages 128 rows into padded smem (coalesced), then lane=row: each thread
// scores its own row (4 heads) from smem. No shuffles; one exp per (row,head).
// Writes e[n] as float4, coalesced. Scores are O(0.05): exp needs no max subtraction.
#define SROWS 128
#define SPAD  132   // row stride in floats: conflict-free for lane=row LDS.128
__global__ void __launch_bounds__(256) k_score(const float* __restrict__ x, int N) {
    extern __shared__ float sm[];
    float* tile = sm;                 // [SROWS][SPAD]
    float* s_Af = sm + SROWS * SPAD;  // [128][4]
    int tid = threadIdx.x;
    int n0 = blockIdx.x * SROWS;
    int nvalid = N - n0; if (nvalid > SROWS) nvalid = SROWS;

    if (tid < 128) *(float4*)&s_Af[tid * 4] = *(const float4*)&g_A[tid * 4];
    // stage 128 rows, coalesced (512B per warp-row)
    #pragma unroll 4
    for (int i = tid; i < SROWS * 32; i += 256) {
        int rr = i >> 5, w = i & 31;
        if (rr < nvalid)
            *(float4*)&tile[rr * SPAD + w * 4] =
                __ldcs((const float4*)x + (size_t)(n0 + rr) * 32 + w);
    }
    __syncthreads();

    if (tid < nvalid) {
        float4 c4 = *(const float4*)g_c;
        const float* row = tile + tid * SPAD;
        float sa0 = 0.f, sa1 = 0.f, sa2 = 0.f, sa3 = 0.f;
        float sb0 = 0.f, sb1 = 0.f, sb2 = 0.f, sb3 = 0.f;
        #pragma unroll 8
        for (int i = 0; i < 32; i++) {
            float4 xv = *(const float4*)&row[i * 4];
            float4 A0 = *(const float4*)&s_Af[(4 * i + 0) * 4];
            float4 A1 = *(const float4*)&s_Af[(4 * i + 1) * 4];
            float4 A2 = *(const float4*)&s_Af[(4 * i + 2) * 4];
            float4 A3 = *(const float4*)&s_Af[(4 * i + 3) * 4];
            sa0 = fmaf(xv.x, A0.x, sa0); sa1 = fmaf(xv.x, A0.y, sa1);
            sa2 = fmaf(xv.x, A0.z, sa2); sa3 = fmaf(xv.x, A0.w, sa3);
            sa0 = fmaf(xv.y, A1.x, sa0); sa1 = fmaf(xv.y, A1.y, sa1);
            sa2 = fmaf(xv.y, A1.z, sa2); sa3 = fmaf(xv.y, A1.w, sa3);
            sb0 = fmaf(xv.z, A2.x, sb0); sb1 = fmaf(xv.z, A2.y, sb1);
            sb2 = fmaf(xv.z, A2.z, sb2); sb3 = fmaf(xv.z, A2.w, sb3);
            sb0 = fmaf(xv.w, A3.x, sb0); sb1 = fmaf(xv.w, A3.y, sb1);
            sb2 = fmaf(xv.w, A3.z, sb2); sb3 = fmaf(xv.w, A3.w, sb3);
        }
        float4 e;
        e.x = __expf(sa0 + sb0 + c4.x);
        e.y = __expf(sa1 + sb1 + c4.y);
        e.z = __expf(sa2 + sb2 + c4.z);
        e.w = __expf(sa3 + sb3 + c4.w);
        *(float4*)&g_e[(size_t)(n0 + tid) * 4] = e;
    }
}

// ---------------- pass B: per-region gather-accumulate + Wv matvec ----------------
// One block per region, 8 warps. Lean inner loop: per row 1 coalesced x-load +
// 1 broadcast e-load + 16 FMA. No shuffles/exp/sync inside. 8 rows unrolled: MLP=16.
#define PCHUNK 1024
__global__ void __launch_bounds__(256) k_pool(const float* __restrict__ x,
                                              const float* __restrict__ Wv,
                                              const float* __restrict__ bv) {
    __shared__ __align__(16) float s_acc[8][512];
    __shared__ float s_den[8][4];
    __shared__ __align__(16) float s_pool[512];
    __shared__ float s_dtot[4];
    __shared__ int   s_idx[PCHUNK];

    int r = blockIdx.x;
    int tid = threadIdx.x, lane = tid & 31, warp = tid >> 5;

    float4 acc0 = make_float4(0.f, 0.f, 0.f, 0.f);
    float4 acc1 = acc0, acc2 = acc0, acc3 = acc0;
    float4 den  = acc0;

    const float4* xp = (const float4*)x;
    const float4* ep = (const float4*)g_e;

    int beg = g_off[r], end = g_off[r + 1];
    for (int cbeg = beg; cbeg < end; cbeg += PCHUNK) {
        int cnt = end - cbeg;
        if (cnt > PCHUNK) cnt = PCHUNK;
        for (int i = tid; i < cnt; i += 256) s_idx[i] = g_perm[cbeg + i];
        __syncthreads();

        for (int base = warp * 8; base < cnt; base += 64) {
            int m = cnt - base;
            if (m >= 8) {
                int n0 = s_idx[base + 0], n1 = s_idx[base + 1];
                int n2 = s_idx[base + 2], n3 = s_idx[base + 3];
                int n4 = s_idx[base + 4], n5 = s_idx[base + 5];
                int n6 = s_idx[base + 6], n7 = s_idx[base + 7];
                float4 x0 = __ldcs(xp + (size_t)n0 * 32 + lane);
                float4 x1 = __ldcs(xp + (size_t)n1 * 32 + lane);
                float4 x2 = __ldcs(xp + (size_t)n2 * 32 + lane);
                float4 x3 = __ldcs(xp + (size_t)n3 * 32 + lane);
                float4 x4 = __ldcs(xp + (size_t)n4 * 32 + lane);
                float4 x5 = __ldcs(xp + (size_t)n5 * 32 + lane);
                float4 x6 = __ldcs(xp + (size_t)n6 * 32 + lane);
                float4 x7 = __ldcs(xp + (size_t)n7 * 32 + lane);
                float4 e0 = __ldg(ep + n0);
                float4 e1 = __ldg(ep + n1);
                float4 e2 = __ldg(ep + n2);
                float4 e3 = __ldg(ep + n3);
                float4 e4 = __ldg(ep + n4);
                float4 e5 = __ldg(ep + n5);
                float4 e6 = __ldg(ep + n6);
                float4 e7 = __ldg(ep + n7);
                #define ROWACC(ee, xx) \
                    acc0.x = fmaf(ee.x, xx.x, acc0.x); acc0.y = fmaf(ee.x, xx.y, acc0.y); \
                    acc0.z = fmaf(ee.x, xx.z, acc0.z); acc0.w = fmaf(ee.x, xx.w, acc0.w); \
                    acc1.x = fmaf(ee.y, xx.x, acc1.x); acc1.y = fmaf(ee.y, xx.y, acc1.y); \
                    acc1.z = fmaf(ee.y, xx.z, acc1.z); acc1.w = fmaf(ee.y, xx.w, acc1.w); \
                    acc2.x = fmaf(ee.z, xx.x, acc2.x); acc2.y = fmaf(ee.z, xx.y, acc2.y); \
                    acc2.z = fmaf(ee.z, xx.z, acc2.z); acc2.w = fmaf(ee.z, xx.w, acc2.w); \
                    acc3.x = fmaf(ee.w, xx.x, acc3.x); acc3.y = fmaf(ee.w, xx.y, acc3.y); \
                    acc3.z = fmaf(ee.w, xx.z, acc3.z); acc3.w = fmaf(ee.w, xx.w, acc3.w); \
                    den.x += ee.x; den.y += ee.y; den.z += ee.z; den.w += ee.w;
                ROWACC(e0, x0) ROWACC(e1, x1) ROWACC(e2, x2) ROWACC(e3, x3)
                ROWACC(e4, x4) ROWACC(e5, x5) ROWACC(e6, x6) ROWACC(e7, x7)
            } else {
                for (int j = 0; j < m; j++) {
                    int n = s_idx[base + j];
                    float4 xv = __ldcs(xp + (size_t)n * 32 + lane);
                    float4 ev = __ldg(ep + n);
                    ROWACC(ev, xv)
                }
            }
        }
        __syncthreads();  // protect s_idx before next chunk overwrite
    }

    // epilogue: cross-warp reduce, normalize, Wv matvec
    *(float4*)&s_acc[warp][0 * 128 + lane * 4] = acc0;
    *(float4*)&s_acc[warp][1 * 128 + lane * 4] = acc1;
    *(float4*)&s_acc[warp][2 * 128 + lane * 4] = acc2;
    *(float4*)&s_acc[warp][3 * 128 + lane * 4] = acc3;
    if (lane == 0) {  // den identical across lanes (broadcast accumulation)
        s_den[warp][0] = den.x; s_den[warp][1] = den.y;
        s_den[warp][2] = den.z; s_den[warp][3] = den.w;
    }
    __syncthreads();
    if (tid < 4) {
        float v = 0.f;
        #pragma unroll
        for (int w = 0; w < 8; w++) v += s_den[w][tid];
        s_dtot[tid] = fmaxf(v, 1e-30f);
    }
    __syncthreads();
    for (int i = tid; i < 512; i += 256) {
        int h = i >> 7;
        float v = 0.f;
        #pragma unroll
        for (int w = 0; w < 8; w++) v += s_acc[w][i];
        s_pool[i] = v / s_dtot[h];
    }
    __syncthreads();
    // pooled[j] = Wv[j,:] . xbar[h(j),:] + bv[j] ; O = q + pooled
    if (tid < 128) {
        int j = tid, h = j >> 5;
        const float4* wr = (const float4*)(Wv + (size_t)j * D);
        const float4* xb = (const float4*)(s_pool + h * D);
        float acc = 0.f;
        #pragma unroll 8
        for (int tt = 0; tt < 32; tt++) {
            float4 w = wr[tt]; float4 b = xb[tt];
            acc = fmaf(w.x, b.x, fmaf(w.y, b.y, fmaf(w.z, b.z, fmaf(w.w, b.w, acc))));
        }
        g_O[r * D + j] = g_qvec[j] + acc + bv[j];
    }
}

// ---------------- fused rFF (O += relu(O@Wo^T + bo)) and h = O2 @ Wg^T ----------------
__global__ void __launch_bounds__(256) k_ff(const float* __restrict__ bo) {
    const int RPB = 16, PAD = 20;
    __shared__ __align__(16) float OsmT[128 * PAD];
    __shared__ __align__(16) float O2T[128 * PAD];
    int r0 = blockIdx.x * RPB;
    int tid = threadIdx.x;
    int j = tid & 127;
    int rr0 = (tid >> 7) * 8;

    for (int i = tid; i < RPB * D; i += 256) {
        int rr = i >> 7, d = i & 127;
        OsmT[d * PAD + rr] = g_O[(r0 + rr) * D + d];
    }
    __syncthreads();

    float acc[8];
    #pragma unroll
    for (int k = 0; k < 8; k++) acc[k] = 0.f;
    for (int d = 0; d < D; d++) {
        float w = g_WoT[d * D + j];
        const float4* o4 = (const float4*)&OsmT[d * PAD + rr0];
        float4 oa = o4[0], ob = o4[1];
        acc[0] = fmaf(w, oa.x, acc[0]); acc[1] = fmaf(w, oa.y, acc[1]);
        acc[2] = fmaf(w, oa.z, acc[2]); acc[3] = fmaf(w, oa.w, acc[3]);
        acc[4] = fmaf(w, ob.x, acc[4]); acc[5] = fmaf(w, ob.y, acc[5]);
        acc[6] = fmaf(w, ob.z, acc[6]); acc[7] = fmaf(w, ob.w, acc[7]);
    }
    float boj = bo[j];
    #pragma unroll
    for (int k = 0; k < 8; k++) {
        float t = acc[k] + boj;
        t = t > 0.f ? t : 0.f;
        O2T[j * PAD + rr0 + k] = OsmT[j * PAD + rr0 + k] + t;
    }
    __syncthreads();
    #pragma unroll
    for (int k = 0; k < 8; k++) acc[k] = 0.f;
    for (int d = 0; d < D; d++) {
        float w = g_WgT[d * D + j];
        const float4* o4 = (const float4*)&O2T[d * PAD + rr0];
        float4 oa = o4[0], ob = o4[1];
        acc[0] = fmaf(w, oa.x, acc[0]); acc[1] = fmaf(w, oa.y, acc[1]);
        acc[2] = fmaf(w, oa.z, acc[2]); acc[3] = fmaf(w, oa.w, acc[3]);
        acc[4] = fmaf(w, ob.x, acc[4]); acc[5] = fmaf(w, ob.y, acc[5]);
        acc[6] = fmaf(w, ob.z, acc[6]); acc[7] = fmaf(w, ob.w, acc[7]);
    }
    #pragma unroll
    for (int k = 0; k < 8; k++) g_hfeat[(r0 + rr0 + k) * D + j] = acc[k];
}

// ---------------- GCN edge scatter (incl. self loops) ----------------
__global__ void k_edge(const int* __restrict__ adj, int E) {
    int idx = blockIdx.x * blockDim.x + threadIdx.x;
    int total = (E + R) * 32;
    if (idx >= total) return;
    int e = idx >> 5, g = idx & 31, d0 = g * 4;
    int s, dt;
    if (e < E) { s = adj[e]; dt = adj[E + e]; }
    else       { s = dt = e - E; }
    float nrm = rsqrtf(g_deg[s]) * rsqrtf(g_deg[dt]);
    float4 hv = *(const float4*)&g_hfeat[s * D + d0];
    float* o = &g_accG[dt * D + d0];
    atomicAdd(o + 0, nrm * hv.x);
    atomicAdd(o + 1, nrm * hv.y);
    atomicAdd(o + 2, nrm * hv.z);
    atomicAdd(o + 3, nrm * hv.w);
}

// ---------------- bias + PReLU epilogue ----------------
__global__ void k_prelu(const float* __restrict__ bg, const float* __restrict__ pw,
                        float* __restrict__ out) {
    int i = blockIdx.x * blockDim.x + threadIdx.x;
    if (i < R * D) {
        int d = i & 127;
        float v = g_accG[i] + bg[d];
        out[i] = v > 0.f ? v : pw[d] * v;
    }
}

// ---------------- launcher ----------------
extern "C" void kernel_launch(void* const* d_in, const int* in_sizes, int n_in,
                              void* d_out, int out_size) {
    const float* x  = (const float*)d_in[0];
    const int* zone = (const int*)d_in[1];
    const int* adj  = (const int*)d_in[2];
    const float* S  = (const float*)d_in[3];
    const float* Wq = (const float*)d_in[4];
    const float* bq = (const float*)d_in[5];
    const float* Wk = (const float*)d_in[6];
    const float* bk = (const float*)d_in[7];
    const float* Wv = (const float*)d_in[8];
    const float* bv = (const float*)d_in[9];
    const float* Wo = (const float*)d_in[10];
    const float* bo = (const float*)d_in[11];
    const float* Wg = (const float*)d_in[12];
    const float* bg = (const float*)d_in[13];
    const float* pw = (const float*)d_in[14];
    float* out = (float*)d_out;
    int N = in_sizes[0] / D;
    int E = in_sizes[2] / 2;

    const int SMEM_SCORE = (SROWS * SPAD + 512) * 4;  // ~68 KB
    cudaFuncSetAttribute(k_score, cudaFuncAttributeMaxDynamicSharedMemorySize, SMEM_SCORE);

    k_init<<<(R * D + 255) / 256, 256>>>();
    k_prep<<<1, 128>>>(S, Wq, bq, Wk, bk, Wo, Wg);
    k_hist_deg<<<(N + E + 255) / 256, 256>>>(zone, adj, N, E);
    k_scan<<<1, 1024>>>();
    k_scatter<<<(N + 255) / 256, 256>>>(zone, N);
    k_score<<<(N + SROWS - 1) / SROWS, 256, SMEM_SCORE>>>(x, N);
    k_pool<<<R, 256>>>(x, Wv, bv);
    k_ff<<<R / 16, 256>>>(bo);
    k_edge<<<((E + R) * 32 + 255) / 256, 256>>>(adj, E);
    k_prelu<<<(R * D + 255) / 256, 256>>>(bg, pw, out);
}